// round 1
// baseline (speedup 1.0000x reference)
#include <cuda_runtime.h>
#include <cuda_bf16.h>
#include <cstdint>

#define BATCH   256
#define FEAT    512
#define HIDDEN  512
#define WVEC    256
#define VOCAB   32000
#define TSTEPS  16
#define CAPLEN  17

// ---------------------------------------------------------------------------
// Scratch layout (single __device__ array, offsets in bytes, all 256-aligned)
// ---------------------------------------------------------------------------
constexpr size_t SZ_VOCABW_BF  = (size_t)VOCAB * HIDDEN * 2;
constexpr size_t SZ_WIH_BF     = (size_t)4 * HIDDEN * WVEC * 2;
constexpr size_t SZ_WHH_BF     = (size_t)4 * HIDDEN * HIDDEN * 2;
constexpr size_t SZ_PROJW_BF   = (size_t)HIDDEN * FEAT * 2;
constexpr size_t SZ_ATTNW_BF   = (size_t)FEAT * HIDDEN * 2;
constexpr size_t SZ_ZTRANSW_BF = (size_t)WVEC * FEAT * 2;
constexpr size_t SZ_FEAT_BF    = (size_t)BATCH * FEAT * 2;
constexpr size_t SZ_H_BF       = (size_t)BATCH * HIDDEN * 2;
constexpr size_t SZ_X_BF       = (size_t)BATCH * WVEC * 2;
constexpr size_t SZ_Z_BF       = (size_t)BATCH * FEAT * 2;
constexpr size_t SZ_C          = (size_t)BATCH * HIDDEN * 4;
constexpr size_t SZ_GATES      = (size_t)BATCH * 4 * HIDDEN * 4;
constexpr size_t SZ_PRE        = (size_t)BATCH * FEAT * 4;
constexpr size_t SZ_BIASC      = (size_t)4 * HIDDEN * 4;
constexpr size_t SZ_ROWSUM     = (size_t)BATCH * 4;
constexpr size_t SZ_TGT        = (size_t)BATCH * 4;

constexpr size_t OFF_VOCABW  = 0;
constexpr size_t OFF_WIH     = OFF_VOCABW  + SZ_VOCABW_BF;
constexpr size_t OFF_WHH     = OFF_WIH     + SZ_WIH_BF;
constexpr size_t OFF_PROJW   = OFF_WHH     + SZ_WHH_BF;
constexpr size_t OFF_ATTNW   = OFF_PROJW   + SZ_PROJW_BF;
constexpr size_t OFF_ZTRANSW = OFF_ATTNW   + SZ_ATTNW_BF;
constexpr size_t OFF_FEATBF  = OFF_ZTRANSW + SZ_ZTRANSW_BF;
constexpr size_t OFF_HBF     = OFF_FEATBF  + SZ_FEAT_BF;
constexpr size_t OFF_XBF     = OFF_HBF     + SZ_H_BF;
constexpr size_t OFF_ZBF     = OFF_XBF     + SZ_X_BF;
constexpr size_t OFF_C       = OFF_ZBF     + SZ_Z_BF;
constexpr size_t OFF_GATES   = OFF_C       + SZ_C;
constexpr size_t OFF_PRE     = OFF_GATES   + SZ_GATES;
constexpr size_t OFF_BIASC   = OFF_PRE     + SZ_PRE;
constexpr size_t OFF_ROWSUM  = OFF_BIASC   + SZ_BIASC;
constexpr size_t OFF_TGTL    = OFF_ROWSUM  + SZ_ROWSUM;
constexpr size_t SCRATCH_TOTAL = OFF_TGTL + SZ_TGT;

__device__ unsigned char g_scratch[SCRATCH_TOTAL];

// ---------------------------------------------------------------------------
// Helpers
// ---------------------------------------------------------------------------
__device__ __forceinline__ float sigmoidf_(float x) { return 1.f / (1.f + __expf(-x)); }

__device__ __forceinline__ void mma16816(float c[4], const uint32_t a[4], const uint32_t b[2]) {
    asm volatile(
        "mma.sync.aligned.m16n8k16.row.col.f32.bf16.bf16.f32 "
        "{%0,%1,%2,%3},{%4,%5,%6,%7},{%8,%9},{%0,%1,%2,%3};\n"
        : "+f"(c[0]), "+f"(c[1]), "+f"(c[2]), "+f"(c[3])
        : "r"(a[0]), "r"(a[1]), "r"(a[2]), "r"(a[3]), "r"(b[0]), "r"(b[1]));
}

// Warp computes a 64(M) x 32(N) tile: 4 m-frags (16) x 4 n-frags (8).
// A: [M][K] row-major bf16, W: [N][K] row-major bf16 (i.e. C = A * W^T).
// Fragments loaded straight from global (L1/L2-served).
__device__ __forceinline__ void mma_tile_loop(
    float acc[4][4][4],
    const __nv_bfloat16* __restrict__ A,
    const __nv_bfloat16* __restrict__ W,
    int K, int wm0, int wn0, int gid, int tid4)
{
    const __nv_bfloat16* arow[8];
#pragma unroll
    for (int mi = 0; mi < 4; mi++) {
        arow[mi * 2]     = A + (size_t)(wm0 + mi * 16 + gid) * K + tid4 * 2;
        arow[mi * 2 + 1] = arow[mi * 2] + 8 * (size_t)K;
    }
    const __nv_bfloat16* brow[4];
#pragma unroll
    for (int ni = 0; ni < 4; ni++)
        brow[ni] = W + (size_t)(wn0 + ni * 8 + gid) * K + tid4 * 2;

    for (int kk = 0; kk < K; kk += 16) {
        uint32_t a[4][4], b[4][2];
#pragma unroll
        for (int mi = 0; mi < 4; mi++) {
            a[mi][0] = *(const uint32_t*)(arow[mi * 2] + kk);
            a[mi][1] = *(const uint32_t*)(arow[mi * 2 + 1] + kk);
            a[mi][2] = *(const uint32_t*)(arow[mi * 2] + kk + 8);
            a[mi][3] = *(const uint32_t*)(arow[mi * 2 + 1] + kk + 8);
        }
#pragma unroll
        for (int ni = 0; ni < 4; ni++) {
            b[ni][0] = *(const uint32_t*)(brow[ni] + kk);
            b[ni][1] = *(const uint32_t*)(brow[ni] + kk + 8);
        }
#pragma unroll
        for (int mi = 0; mi < 4; mi++)
#pragma unroll
            for (int ni = 0; ni < 4; ni++)
                mma16816(acc[mi][ni], a[mi], b[ni]);
    }
}

// ---------------------------------------------------------------------------
// Generic bf16 GEMM: C = A1*W1^T (+ A2*W2^T) (+ bias) (+ gatherTab[idx[row]]),
// outputs fp32 and/or bf16. Block tile (WARPS_M*64) x (WARPS_N*32).
// ---------------------------------------------------------------------------
template <int WARPS_M, int WARPS_N>
__global__ void __launch_bounds__(WARPS_M * WARPS_N * 32)
gemm_kernel(const __nv_bfloat16* __restrict__ A1, const __nv_bfloat16* __restrict__ W1, int K1,
            const __nv_bfloat16* __restrict__ A2, const __nv_bfloat16* __restrict__ W2, int K2,
            const float* __restrict__ bias,
            const float* __restrict__ gTab, const int* __restrict__ gIdx, int gStride, int gLd,
            float* __restrict__ outF, __nv_bfloat16* __restrict__ outB, int N)
{
    int warp = threadIdx.x >> 5, lane = threadIdx.x & 31;
    int gid = lane >> 2, tid4 = lane & 3;
    int wm0 = blockIdx.x * (WARPS_M * 64) + (warp % WARPS_M) * 64;
    int wn0 = blockIdx.y * (WARPS_N * 32) + (warp / WARPS_M) * 32;

    float acc[4][4][4];
#pragma unroll
    for (int i = 0; i < 4; i++)
#pragma unroll
        for (int j = 0; j < 4; j++)
#pragma unroll
            for (int k = 0; k < 4; k++) acc[i][j][k] = 0.f;

    mma_tile_loop(acc, A1, W1, K1, wm0, wn0, gid, tid4);
    if (A2) mma_tile_loop(acc, A2, W2, K2, wm0, wn0, gid, tid4);

#pragma unroll
    for (int mi = 0; mi < 4; mi++)
#pragma unroll
        for (int ci = 0; ci < 2; ci++) {
            int row = wm0 + mi * 16 + gid + ci * 8;
            const float* grow = nullptr;
            if (gIdx) grow = gTab + (size_t)gIdx[row * gStride] * gLd;
#pragma unroll
            for (int ni = 0; ni < 4; ni++)
#pragma unroll
                for (int cj = 0; cj < 2; cj++) {
                    int col = wn0 + ni * 8 + tid4 * 2 + cj;
                    float v = acc[mi][ni][ci * 2 + cj];
                    if (bias) v += bias[col];
                    if (grow) v += grow[col];
                    size_t o = (size_t)row * N + col;
                    if (outF) outF[o] = v;
                    if (outB) outB[o] = __float2bfloat16(v);
                }
        }
}

// ---------------------------------------------------------------------------
// Vocab GEMM with fused exp / row-sum / target-logit epilogue.
// Block tile 128x128, 8 warps (2 in M, 4 in N), grid (2, 250).
// logits are ~N(0, 0.14): no max-subtraction needed for a safe expf.
// ---------------------------------------------------------------------------
__global__ void __launch_bounds__(256)
vocab_kernel(const __nv_bfloat16* __restrict__ hbf, const __nv_bfloat16* __restrict__ Wv,
             const float* __restrict__ vb, const int* __restrict__ tgtBase,
             float* __restrict__ rowsum, float* __restrict__ tgtlogit)
{
    int warp = threadIdx.x >> 5, lane = threadIdx.x & 31;
    int gid = lane >> 2, tid4 = lane & 3;
    int wm0 = blockIdx.x * 128 + (warp & 1) * 64;
    int wn0 = blockIdx.y * 128 + (warp >> 1) * 32;

    float acc[4][4][4];
#pragma unroll
    for (int i = 0; i < 4; i++)
#pragma unroll
        for (int j = 0; j < 4; j++)
#pragma unroll
            for (int k = 0; k < 4; k++) acc[i][j][k] = 0.f;

    mma_tile_loop(acc, hbf, Wv, HIDDEN, wm0, wn0, gid, tid4);

#pragma unroll
    for (int mi = 0; mi < 4; mi++)
#pragma unroll
        for (int ci = 0; ci < 2; ci++) {
            int row = wm0 + mi * 16 + gid + ci * 8;
            int tgt = tgtBase[row * CAPLEN];
            float s = 0.f;
#pragma unroll
            for (int ni = 0; ni < 4; ni++)
#pragma unroll
                for (int cj = 0; cj < 2; cj++) {
                    int col = wn0 + ni * 8 + tid4 * 2 + cj;
                    float v = acc[mi][ni][ci * 2 + cj] + vb[col];
                    s += __expf(v);
                    if (col == tgt) tgtlogit[row] = v;  // unique writer per row
                }
            s += __shfl_xor_sync(0xffffffffu, s, 1);
            s += __shfl_xor_sync(0xffffffffu, s, 2);
            if (tid4 == 0) atomicAdd(&rowsum[row], s);
        }
}

// ---------------------------------------------------------------------------
// LSTM elementwise: gates [B][4H] -> c, h (bf16); also zero rowsum for this step
// ---------------------------------------------------------------------------
__global__ void lstm_kernel(const float* __restrict__ gates, float* __restrict__ c,
                            __nv_bfloat16* __restrict__ hbf, float* __restrict__ rowsum)
{
    int idx = blockIdx.x * blockDim.x + threadIdx.x;  // 131072
    int b = idx >> 9, u = idx & 511;
    const float* g = gates + ((size_t)b << 11);
    float ig = sigmoidf_(g[u]);
    float fg = sigmoidf_(g[512 + u]);
    float gg = tanhf(g[1024 + u]);
    float og = sigmoidf_(g[1536 + u]);
    float cn = fg * c[idx] + ig * gg;
    float hn = og * tanhf(cn);
    c[idx] = cn;
    hbf[idx] = __float2bfloat16(hn);
    if (idx < BATCH) rowsum[idx] = 0.f;
}

// ---------------------------------------------------------------------------
// Softmax over attn pre-activations -> z = a * features (bf16); plus the
// per-row loss contribution for this step (if lossOut != nullptr).
// ---------------------------------------------------------------------------
__global__ void __launch_bounds__(128)
softz_kernel(const float* __restrict__ pre, const float* __restrict__ features,
             __nv_bfloat16* __restrict__ zbf,
             const float* __restrict__ rowsum, const float* __restrict__ tgtlogit,
             const int* __restrict__ tgtBase, float* __restrict__ lossOut)
{
    int b = blockIdx.x, t = threadIdx.x;
    __shared__ float red[128];
    float v[4];
    float mx = -1e30f;
#pragma unroll
    for (int j = 0; j < 4; j++) {
        v[j] = pre[b * 512 + t + j * 128];
        mx = fmaxf(mx, v[j]);
    }
    red[t] = mx;
    __syncthreads();
    for (int s = 64; s > 0; s >>= 1) {
        if (t < s) red[t] = fmaxf(red[t], red[t + s]);
        __syncthreads();
    }
    mx = red[0];
    __syncthreads();
    float sum = 0.f;
#pragma unroll
    for (int j = 0; j < 4; j++) {
        v[j] = __expf(v[j] - mx);
        sum += v[j];
    }
    red[t] = sum;
    __syncthreads();
    for (int s = 64; s > 0; s >>= 1) {
        if (t < s) red[t] += red[t + s];
        __syncthreads();
    }
    float inv = 1.f / red[0];
#pragma unroll
    for (int j = 0; j < 4; j++) {
        int f = t + j * 128;
        zbf[b * 512 + f] = __float2bfloat16(v[j] * inv * features[b * 512 + f]);
    }
    if (t == 0 && lossOut) {
        int tgt = tgtBase[b * CAPLEN];
        if (tgt != 0) {
            float l = logf(rowsum[b]) - tgtlogit[b];
            atomicAdd(lossOut, l * (1.f / BATCH));
        }
    }
}

// ---------------------------------------------------------------------------
// fp32 -> bf16 convert, and misc init
// ---------------------------------------------------------------------------
__global__ void convert_kernel(const float* __restrict__ src, __nv_bfloat16* __restrict__ dst, int n)
{
    int i = (blockIdx.x * blockDim.x + threadIdx.x) * 2;
    if (i < n) {
        float2 f = *(const float2*)(src + i);
        *(__nv_bfloat162*)(dst + i) = __float22bfloat162_rn(f);
    }
}

__global__ void init_kernel(float* __restrict__ c, float* __restrict__ biasc,
                            const float* __restrict__ b_ih, const float* __restrict__ b_hh,
                            float* __restrict__ out)
{
    int idx = blockIdx.x * blockDim.x + threadIdx.x;  // 131072
    c[idx] = 0.f;
    if (idx < 4 * HIDDEN) biasc[idx] = b_ih[idx] + b_hh[idx];
    if (idx == 0) out[0] = 0.f;
}

// ---------------------------------------------------------------------------
// Host launcher — graph-capturable, allocation-free, deterministic work
// ---------------------------------------------------------------------------
extern "C" void kernel_launch(void* const* d_in, const int* in_sizes, int n_in,
                              void* d_out, int out_size)
{
    (void)in_sizes; (void)n_in; (void)out_size;
    const float* features = (const float*)d_in[0];
    const int*   captions = (const int*)d_in[1];
    const float* embed_W  = (const float*)d_in[2];
    const float* proj_W   = (const float*)d_in[3];
    const float* proj_b   = (const float*)d_in[4];
    const float* vocab_W  = (const float*)d_in[5];
    const float* vocab_b  = (const float*)d_in[6];
    const float* attn_W   = (const float*)d_in[7];
    const float* attn_b   = (const float*)d_in[8];
    const float* ztrans_W = (const float*)d_in[9];
    const float* ztrans_b = (const float*)d_in[10];
    const float* W_ih     = (const float*)d_in[11];
    const float* W_hh     = (const float*)d_in[12];
    const float* b_ih     = (const float*)d_in[13];
    const float* b_hh     = (const float*)d_in[14];
    float* out = (float*)d_out;

    void* basev = nullptr;
    cudaGetSymbolAddress(&basev, g_scratch);
    char* p = (char*)basev;
    __nv_bfloat16* vocabW_bf  = (__nv_bfloat16*)(p + OFF_VOCABW);
    __nv_bfloat16* Wih_bf     = (__nv_bfloat16*)(p + OFF_WIH);
    __nv_bfloat16* Whh_bf     = (__nv_bfloat16*)(p + OFF_WHH);
    __nv_bfloat16* projW_bf   = (__nv_bfloat16*)(p + OFF_PROJW);
    __nv_bfloat16* attnW_bf   = (__nv_bfloat16*)(p + OFF_ATTNW);
    __nv_bfloat16* ztransW_bf = (__nv_bfloat16*)(p + OFF_ZTRANSW);
    __nv_bfloat16* feat_bf    = (__nv_bfloat16*)(p + OFF_FEATBF);
    __nv_bfloat16* h_bf       = (__nv_bfloat16*)(p + OFF_HBF);
    __nv_bfloat16* x_bf       = (__nv_bfloat16*)(p + OFF_XBF);
    __nv_bfloat16* z_bf       = (__nv_bfloat16*)(p + OFF_ZBF);
    float* cbuf     = (float*)(p + OFF_C);
    float* gates    = (float*)(p + OFF_GATES);
    float* pre      = (float*)(p + OFF_PRE);
    float* biasc    = (float*)(p + OFF_BIASC);
    float* rowsum   = (float*)(p + OFF_ROWSUM);
    float* tgtlogit = (float*)(p + OFF_TGTL);

    auto cvt = [&](const float* s, __nv_bfloat16* d, int n) {
        convert_kernel<<<(n / 2 + 255) / 256, 256>>>(s, d, n);
    };
    cvt(vocab_W, vocabW_bf, VOCAB * HIDDEN);
    cvt(W_ih, Wih_bf, 4 * HIDDEN * WVEC);
    cvt(W_hh, Whh_bf, 4 * HIDDEN * HIDDEN);
    cvt(proj_W, projW_bf, HIDDEN * FEAT);
    cvt(attn_W, attnW_bf, FEAT * HIDDEN);
    cvt(ztrans_W, ztransW_bf, WVEC * FEAT);
    cvt(features, feat_bf, BATCH * FEAT);
    init_kernel<<<512, 256>>>(cbuf, biasc, b_ih, b_hh, out);

    // h0 = features @ proj_W^T + proj_b  (bf16 out only; h is consumed as bf16)
    gemm_kernel<2, 2><<<dim3(2, 8), 128>>>(
        feat_bf, projW_bf, FEAT, nullptr, nullptr, 0, proj_b,
        nullptr, nullptr, 0, 0, nullptr, h_bf, HIDDEN);

    // initial attention -> z0
    gemm_kernel<2, 2><<<dim3(2, 8), 128>>>(
        h_bf, attnW_bf, HIDDEN, nullptr, nullptr, 0, attn_b,
        nullptr, nullptr, 0, 0, pre, nullptr, FEAT);
    softz_kernel<<<BATCH, 128>>>(pre, features, z_bf, nullptr, nullptr, nullptr, nullptr);

    for (int t = 0; t < TSTEPS; t++) {
        // x = embed_W[word_t] + z @ ztrans_W^T + ztrans_b   -> bf16
        gemm_kernel<2, 2><<<dim3(2, 4), 128>>>(
            z_bf, ztransW_bf, FEAT, nullptr, nullptr, 0, ztrans_b,
            embed_W, captions + t, CAPLEN, WVEC, nullptr, x_bf, WVEC);

        // gates = x @ W_ih^T + h @ W_hh^T + (b_ih + b_hh)
        gemm_kernel<2, 2><<<dim3(2, 32), 128>>>(
            x_bf, Wih_bf, WVEC, h_bf, Whh_bf, HIDDEN, biasc,
            nullptr, nullptr, 0, 0, gates, nullptr, 4 * HIDDEN);

        // LSTM cell -> c, h_bf; zero rowsum for vocab pass
        lstm_kernel<<<512, 256>>>(gates, cbuf, h_bf, rowsum);

        // logits = h @ vocab_W^T + vocab_b; fused sum(exp) + target gather
        vocab_kernel<<<dim3(2, VOCAB / 128), 256>>>(
            h_bf, vocabW_bf, vocab_b, captions + t + 1, rowsum, tgtlogit);

        // attention pre-activations for z_{t+1}
        gemm_kernel<2, 2><<<dim3(2, 8), 128>>>(
            h_bf, attnW_bf, HIDDEN, nullptr, nullptr, 0, attn_b,
            nullptr, nullptr, 0, 0, pre, nullptr, FEAT);

        // softmax -> z_bf, plus loss_t accumulation (masked), /BATCH folded in
        softz_kernel<<<BATCH, 128>>>(pre, features, z_bf, rowsum, tgtlogit,
                                     captions + t + 1, out);
    }
}

// round 4
// speedup vs baseline: 2.2323x; 2.2323x over previous
#include <cuda_runtime.h>
#include <cuda_bf16.h>
#include <cstdint>

#define BATCH   256
#define FEAT    512
#define HIDDEN  512
#define WVEC    256
#define VOCAB   32000
#define TSTEPS  16
#define CAPLEN  17

// ---------------------------------------------------------------------------
// Fragment-native layout ("frag"): for a [R][K] bf16 matrix (R%8==0, K%32==0),
// element (row,k) lives at:
//   block = (row/8)*(K/32) + (k/32)          (512B blocks)
//   slot  = (row%8)*4 + (k/8)%4              (16B granules, = lane id)
//   byte  = (k%8)*2
// One warp's fragment load for an 8-row x 32-k tile is then 32 consecutive
// 16B granules -> a single fully-coalesced 512B access.
// ---------------------------------------------------------------------------
__device__ __forceinline__ size_t frag_off(int row, int k, int K) {
    return ((size_t)(row >> 3) * (K >> 5) + (k >> 5)) * 256
         + (size_t)(((row & 7) * 4 + ((k >> 3) & 3)) * 8 + (k & 7));
}

// ---------------------------------------------------------------------------
// Scratch layout (single __device__ array, offsets in bytes, all 256-aligned)
// ---------------------------------------------------------------------------
constexpr size_t SZ_VOCABW_BF  = (size_t)VOCAB * HIDDEN * 2;
constexpr size_t SZ_WIH_BF     = (size_t)4 * HIDDEN * WVEC * 2;
constexpr size_t SZ_WHH_BF     = (size_t)4 * HIDDEN * HIDDEN * 2;
constexpr size_t SZ_PROJW_BF   = (size_t)HIDDEN * FEAT * 2;
constexpr size_t SZ_ATTNW_BF   = (size_t)FEAT * HIDDEN * 2;
constexpr size_t SZ_ZTRANSW_BF = (size_t)WVEC * FEAT * 2;
constexpr size_t SZ_FEAT_BF    = (size_t)BATCH * FEAT * 2;
constexpr size_t SZ_H_BF       = (size_t)BATCH * HIDDEN * 2;
constexpr size_t SZ_X_BF       = (size_t)BATCH * WVEC * 2;
constexpr size_t SZ_Z_BF       = (size_t)BATCH * FEAT * 2;
constexpr size_t SZ_C          = (size_t)BATCH * HIDDEN * 4;
constexpr size_t SZ_GATES      = (size_t)BATCH * 4 * HIDDEN * 4;
constexpr size_t SZ_PRE        = (size_t)BATCH * FEAT * 4;
constexpr size_t SZ_BIASC      = (size_t)4 * HIDDEN * 4;
constexpr size_t SZ_ROWSUM     = (size_t)BATCH * 4;
constexpr size_t SZ_TGT        = (size_t)BATCH * 4;

constexpr size_t OFF_VOCABW  = 0;
constexpr size_t OFF_WIH     = OFF_VOCABW  + SZ_VOCABW_BF;
constexpr size_t OFF_WHH     = OFF_WIH     + SZ_WIH_BF;
constexpr size_t OFF_PROJW   = OFF_WHH     + SZ_WHH_BF;
constexpr size_t OFF_ATTNW   = OFF_PROJW   + SZ_PROJW_BF;
constexpr size_t OFF_ZTRANSW = OFF_ATTNW   + SZ_ATTNW_BF;
constexpr size_t OFF_FEATBF  = OFF_ZTRANSW + SZ_ZTRANSW_BF;
constexpr size_t OFF_HBF     = OFF_FEATBF  + SZ_FEAT_BF;
constexpr size_t OFF_XBF     = OFF_HBF     + SZ_H_BF;
constexpr size_t OFF_ZBF     = OFF_XBF     + SZ_X_BF;
constexpr size_t OFF_C       = OFF_ZBF     + SZ_Z_BF;
constexpr size_t OFF_GATES   = OFF_C       + SZ_C;
constexpr size_t OFF_PRE     = OFF_GATES   + SZ_GATES;
constexpr size_t OFF_BIASC   = OFF_PRE     + SZ_PRE;
constexpr size_t OFF_ROWSUM  = OFF_BIASC   + SZ_BIASC;
constexpr size_t OFF_TGTL    = OFF_ROWSUM  + SZ_ROWSUM;
constexpr size_t SCRATCH_TOTAL = OFF_TGTL + SZ_TGT;

__device__ __align__(1024) unsigned char g_scratch[SCRATCH_TOTAL];

// ---------------------------------------------------------------------------
// mma.sync bf16 core (sm_80+; works with plain sm_100 ptxas target)
// ---------------------------------------------------------------------------
__device__ __forceinline__ float sigmoidf_(float x) { return 1.f / (1.f + __expf(-x)); }

__device__ __forceinline__ uint32_t bf2_to_u32(float lo, float hi) {
    __nv_bfloat162 b = __floats2bfloat162_rn(lo, hi);
    return *reinterpret_cast<uint32_t*>(&b);
}

__device__ __forceinline__ void mma16816(float c[4], uint32_t a0, uint32_t a1,
                                         uint32_t a2, uint32_t a3, uint32_t b0, uint32_t b1) {
    asm volatile(
        "mma.sync.aligned.m16n8k16.row.col.f32.bf16.bf16.f32 "
        "{%0,%1,%2,%3},{%4,%5,%6,%7},{%8,%9},{%0,%1,%2,%3};\n"
        : "+f"(c[0]), "+f"(c[1]), "+f"(c[2]), "+f"(c[3])
        : "r"(a0), "r"(a1), "r"(a2), "r"(a3), "r"(b0), "r"(b1));
}

struct Frags {
    uint4 al[4], ah[4], bv[4];
};

__device__ __forceinline__ void frag_load(Frags& f,
    const __nv_bfloat16* const a0p[4], size_t a1off,
    const __nv_bfloat16* const bp[4], int off)
{
#pragma unroll
    for (int mi = 0; mi < 4; mi++) {
        f.al[mi] = *(const uint4*)(a0p[mi] + off);
        f.ah[mi] = *(const uint4*)(a0p[mi] + a1off + off);
    }
#pragma unroll
    for (int ni = 0; ni < 4; ni++)
        f.bv[ni] = *(const uint4*)(bp[ni] + off);
}

__device__ __forceinline__ void frag_mma(float acc[4][4][4], const Frags& f)
{
#pragma unroll
    for (int mi = 0; mi < 4; mi++)
#pragma unroll
        for (int ni = 0; ni < 4; ni++) {
            mma16816(acc[mi][ni], f.al[mi].x, f.ah[mi].x, f.al[mi].y, f.ah[mi].y,
                     f.bv[ni].x, f.bv[ni].y);
            mma16816(acc[mi][ni], f.al[mi].z, f.ah[mi].z, f.al[mi].w, f.ah[mi].w,
                     f.bv[ni].z, f.bv[ni].w);
        }
}

// Warp computes 64(M) x 32(N). A and W both in frag layout. Double-buffered
// register prefetch over k32 chunks. K-permutation is shared between A and B
// lanes, so the GEMM result is exact.
__device__ __forceinline__ void mma_tile_loop(
    float acc[4][4][4],
    const __nv_bfloat16* __restrict__ A,
    const __nv_bfloat16* __restrict__ W,
    int K, int wm0, int wn0, int lane)
{
    const int kb = K >> 5;                 // k32 blocks per 8-row group
    const size_t a1off = (size_t)kb * 256; // next 8-row group
    const __nv_bfloat16* a0p[4];
    const __nv_bfloat16* bp[4];
#pragma unroll
    for (int mi = 0; mi < 4; mi++)
        a0p[mi] = A + (size_t)((wm0 + mi * 16) >> 3) * kb * 256 + lane * 8;
#pragma unroll
    for (int ni = 0; ni < 4; ni++)
        bp[ni] = W + (size_t)((wn0 >> 3) + ni) * kb * 256 + lane * 8;

    Frags f0, f1;
    frag_load(f0, a0p, a1off, bp, 0);
    for (int it = 0; it < kb; it += 2) {   // kb is even (K = 256 or 512)
        frag_load(f1, a0p, a1off, bp, (it + 1) * 256);
        frag_mma(acc, f0);
        if (it + 2 < kb) frag_load(f0, a0p, a1off, bp, (it + 2) * 256);
        frag_mma(acc, f1);
    }
}

// ---------------------------------------------------------------------------
// Generic bf16 GEMM: C = A1*W1^T (+ A2*W2^T) (+ bias) (+ gatherTab[idx[row]]),
// A/W in frag layout; outF row-major fp32, outB frag-layout bf16.
// Block tile (WARPS_M*64) x (WARPS_N*32).
// ---------------------------------------------------------------------------
template <int WARPS_M, int WARPS_N>
__global__ void __launch_bounds__(WARPS_M * WARPS_N * 32)
gemm_kernel(const __nv_bfloat16* __restrict__ A1, const __nv_bfloat16* __restrict__ W1, int K1,
            const __nv_bfloat16* __restrict__ A2, const __nv_bfloat16* __restrict__ W2, int K2,
            const float* __restrict__ bias,
            const float* __restrict__ gTab, const int* __restrict__ gIdx, int gStride, int gLd,
            float* __restrict__ outF, __nv_bfloat16* __restrict__ outB, int N)
{
    int warp = threadIdx.x >> 5, lane = threadIdx.x & 31;
    int gid = lane >> 2, tid4 = lane & 3;
    int wm0 = blockIdx.x * (WARPS_M * 64) + (warp % WARPS_M) * 64;
    int wn0 = blockIdx.y * (WARPS_N * 32) + (warp / WARPS_M) * 32;

    float acc[4][4][4];
#pragma unroll
    for (int i = 0; i < 4; i++)
#pragma unroll
        for (int j = 0; j < 4; j++)
#pragma unroll
            for (int k = 0; k < 4; k++) acc[i][j][k] = 0.f;

    mma_tile_loop(acc, A1, W1, K1, wm0, wn0, lane);
    if (A2) mma_tile_loop(acc, A2, W2, K2, wm0, wn0, lane);

#pragma unroll
    for (int mi = 0; mi < 4; mi++)
#pragma unroll
        for (int ci = 0; ci < 2; ci++) {
            int row = wm0 + mi * 16 + gid + ci * 8;
            const float* grow = nullptr;
            if (gIdx) grow = gTab + (size_t)gIdx[row * gStride] * gLd;
#pragma unroll
            for (int ni = 0; ni < 4; ni++) {
                int col0 = wn0 + ni * 8 + tid4 * 2;
                float v0 = acc[mi][ni][ci * 2 + 0];
                float v1 = acc[mi][ni][ci * 2 + 1];
                if (bias) { v0 += bias[col0]; v1 += bias[col0 + 1]; }
                if (grow) { v0 += grow[col0]; v1 += grow[col0 + 1]; }
                if (outF) {
                    outF[(size_t)row * N + col0]     = v0;
                    outF[(size_t)row * N + col0 + 1] = v1;
                }
                if (outB) {
                    uint32_t pr = bf2_to_u32(v0, v1);
                    *(uint32_t*)(outB + frag_off(row, col0, N)) = pr;
                }
            }
        }
}

// ---------------------------------------------------------------------------
// Vocab GEMM (128x128 CTA tile, 8 warps) + fused exp/rowsum/target epilogue.
// logits ~N(0,0.14): expf without max subtraction is safe.
// ---------------------------------------------------------------------------
__global__ void __launch_bounds__(256)
vocab_kernel(const __nv_bfloat16* __restrict__ hbf, const __nv_bfloat16* __restrict__ Wv,
             const float* __restrict__ vb, const int* __restrict__ tgtBase,
             float* __restrict__ rowsum, float* __restrict__ tgtlogit)
{
    int warp = threadIdx.x >> 5, lane = threadIdx.x & 31;
    int gid = lane >> 2, tid4 = lane & 3;
    int wm0 = blockIdx.x * 128 + (warp & 1) * 64;
    int wn0 = blockIdx.y * 128 + (warp >> 1) * 32;

    float acc[4][4][4];
#pragma unroll
    for (int i = 0; i < 4; i++)
#pragma unroll
        for (int j = 0; j < 4; j++)
#pragma unroll
            for (int k = 0; k < 4; k++) acc[i][j][k] = 0.f;

    mma_tile_loop(acc, hbf, Wv, HIDDEN, wm0, wn0, lane);

#pragma unroll
    for (int mi = 0; mi < 4; mi++)
#pragma unroll
        for (int ci = 0; ci < 2; ci++) {
            int row = wm0 + mi * 16 + gid + ci * 8;
            int tgt = tgtBase[row * CAPLEN];
            float s = 0.f;
#pragma unroll
            for (int ni = 0; ni < 4; ni++)
#pragma unroll
                for (int cj = 0; cj < 2; cj++) {
                    int col = wn0 + ni * 8 + tid4 * 2 + cj;
                    float v = acc[mi][ni][ci * 2 + cj] + vb[col];
                    s += __expf(v);
                    if (col == tgt) tgtlogit[row] = v;  // unique writer per row
                }
            s += __shfl_xor_sync(0xffffffffu, s, 1);
            s += __shfl_xor_sync(0xffffffffu, s, 2);
            if (tid4 == 0) atomicAdd(&rowsum[row], s);
        }
}

// ---------------------------------------------------------------------------
// LSTM elementwise: gates [B][4H] -> c (fp32), h (bf16 frag); zero rowsum
// ---------------------------------------------------------------------------
__global__ void lstm_kernel(const float* __restrict__ gates, float* __restrict__ c,
                            __nv_bfloat16* __restrict__ hbf, float* __restrict__ rowsum)
{
    int idx = blockIdx.x * blockDim.x + threadIdx.x;  // 131072
    int b = idx >> 9, u = idx & 511;
    const float* g = gates + ((size_t)b << 11);
    float ig = sigmoidf_(g[u]);
    float fg = sigmoidf_(g[512 + u]);
    float gg = tanhf(g[1024 + u]);
    float og = sigmoidf_(g[1536 + u]);
    float cn = fg * c[idx] + ig * gg;
    float hn = og * tanhf(cn);
    c[idx] = cn;
    hbf[frag_off(b, u, HIDDEN)] = __float2bfloat16(hn);
    if (idx < BATCH) rowsum[idx] = 0.f;
}

// ---------------------------------------------------------------------------
// Softmax over attn pre-activations -> z = a * features (bf16 frag); plus the
// per-row masked loss contribution (if lossOut != nullptr).
// ---------------------------------------------------------------------------
__global__ void __launch_bounds__(128)
softz_kernel(const float* __restrict__ pre, const float* __restrict__ features,
             __nv_bfloat16* __restrict__ zbf,
             const float* __restrict__ rowsum, const float* __restrict__ tgtlogit,
             const int* __restrict__ tgtBase, float* __restrict__ lossOut)
{
    int b = blockIdx.x, t = threadIdx.x;
    __shared__ float red[128];
    float v[4];
    float mx = -1e30f;
#pragma unroll
    for (int j = 0; j < 4; j++) {
        v[j] = pre[b * 512 + t + j * 128];
        mx = fmaxf(mx, v[j]);
    }
    red[t] = mx;
    __syncthreads();
    for (int s = 64; s > 0; s >>= 1) {
        if (t < s) red[t] = fmaxf(red[t], red[t + s]);
        __syncthreads();
    }
    mx = red[0];
    __syncthreads();
    float sum = 0.f;
#pragma unroll
    for (int j = 0; j < 4; j++) {
        v[j] = __expf(v[j] - mx);
        sum += v[j];
    }
    red[t] = sum;
    __syncthreads();
    for (int s = 64; s > 0; s >>= 1) {
        if (t < s) red[t] += red[t + s];
        __syncthreads();
    }
    float inv = 1.f / red[0];
#pragma unroll
    for (int j = 0; j < 4; j++) {
        int f = t + j * 128;
        zbf[frag_off(b, f, FEAT)] = __float2bfloat16(v[j] * inv * features[b * 512 + f]);
    }
    if (t == 0 && lossOut) {
        int tgt = tgtBase[b * CAPLEN];
        if (tgt != 0) {
            float l = logf(rowsum[b]) - tgtlogit[b];
            atomicAdd(lossOut, l * (1.f / BATCH));
        }
    }
}

// ---------------------------------------------------------------------------
// fp32 row-major -> bf16 frag-layout convert (one 16B granule per thread)
// ---------------------------------------------------------------------------
__global__ void convert_frag_kernel(const float* __restrict__ src,
                                    __nv_bfloat16* __restrict__ dst, int K, int total)
{
    int g = blockIdx.x * blockDim.x + threadIdx.x;
    if (g >= total) return;
    int kq = K >> 3;
    int row = g / kq;
    int k = (g - row * kq) * 8;
    const float* s = src + (size_t)row * K + k;
    float4 f0 = *(const float4*)s;
    float4 f1 = *(const float4*)(s + 4);
    uint4 o;
    o.x = bf2_to_u32(f0.x, f0.y);
    o.y = bf2_to_u32(f0.z, f0.w);
    o.z = bf2_to_u32(f1.x, f1.y);
    o.w = bf2_to_u32(f1.z, f1.w);
    *(uint4*)(dst + frag_off(row, k, K)) = o;
}

__global__ void init_kernel(float* __restrict__ c, float* __restrict__ biasc,
                            const float* __restrict__ b_ih, const float* __restrict__ b_hh,
                            float* __restrict__ out)
{
    int idx = blockIdx.x * blockDim.x + threadIdx.x;  // 131072
    c[idx] = 0.f;
    if (idx < 4 * HIDDEN) biasc[idx] = b_ih[idx] + b_hh[idx];
    if (idx == 0) out[0] = 0.f;
}

// ---------------------------------------------------------------------------
// Host launcher — graph-capturable, allocation-free, deterministic
// ---------------------------------------------------------------------------
extern "C" void kernel_launch(void* const* d_in, const int* in_sizes, int n_in,
                              void* d_out, int out_size)
{
    (void)in_sizes; (void)n_in; (void)out_size;
    const float* features = (const float*)d_in[0];
    const int*   captions = (const int*)d_in[1];
    const float* embed_W  = (const float*)d_in[2];
    const float* proj_W   = (const float*)d_in[3];
    const float* proj_b   = (const float*)d_in[4];
    const float* vocab_W  = (const float*)d_in[5];
    const float* vocab_b  = (const float*)d_in[6];
    const float* attn_W   = (const float*)d_in[7];
    const float* attn_b   = (const float*)d_in[8];
    const float* ztrans_W = (const float*)d_in[9];
    const float* ztrans_b = (const float*)d_in[10];
    const float* W_ih     = (const float*)d_in[11];
    const float* W_hh     = (const float*)d_in[12];
    const float* b_ih     = (const float*)d_in[13];
    const float* b_hh     = (const float*)d_in[14];
    float* out = (float*)d_out;

    void* basev = nullptr;
    cudaGetSymbolAddress(&basev, g_scratch);
    char* p = (char*)basev;
    __nv_bfloat16* vocabW_bf  = (__nv_bfloat16*)(p + OFF_VOCABW);
    __nv_bfloat16* Wih_bf     = (__nv_bfloat16*)(p + OFF_WIH);
    __nv_bfloat16* Whh_bf     = (__nv_bfloat16*)(p + OFF_WHH);
    __nv_bfloat16* projW_bf   = (__nv_bfloat16*)(p + OFF_PROJW);
    __nv_bfloat16* attnW_bf   = (__nv_bfloat16*)(p + OFF_ATTNW);
    __nv_bfloat16* ztransW_bf = (__nv_bfloat16*)(p + OFF_ZTRANSW);
    __nv_bfloat16* feat_bf    = (__nv_bfloat16*)(p + OFF_FEATBF);
    __nv_bfloat16* h_bf       = (__nv_bfloat16*)(p + OFF_HBF);
    __nv_bfloat16* x_bf       = (__nv_bfloat16*)(p + OFF_XBF);
    __nv_bfloat16* z_bf       = (__nv_bfloat16*)(p + OFF_ZBF);
    float* cbuf     = (float*)(p + OFF_C);
    float* gates    = (float*)(p + OFF_GATES);
    float* pre      = (float*)(p + OFF_PRE);
    float* biasc    = (float*)(p + OFF_BIASC);
    float* rowsum   = (float*)(p + OFF_ROWSUM);
    float* tgtlogit = (float*)(p + OFF_TGTL);

    auto cvt = [&](const float* s, __nv_bfloat16* d, int rows, int K) {
        int total = rows * K / 8;
        convert_frag_kernel<<<(total + 255) / 256, 256>>>(s, d, K, total);
    };
    cvt(vocab_W, vocabW_bf, VOCAB, HIDDEN);
    cvt(W_ih, Wih_bf, 4 * HIDDEN, WVEC);
    cvt(W_hh, Whh_bf, 4 * HIDDEN, HIDDEN);
    cvt(proj_W, projW_bf, HIDDEN, FEAT);
    cvt(attn_W, attnW_bf, FEAT, HIDDEN);
    cvt(ztrans_W, ztransW_bf, WVEC, FEAT);
    cvt(features, feat_bf, BATCH, FEAT);
    init_kernel<<<512, 256>>>(cbuf, biasc, b_ih, b_hh, out);

    // h0 = features @ proj_W^T + proj_b  -> h (bf16 frag)
    gemm_kernel<2, 2><<<dim3(2, 8), 128>>>(
        feat_bf, projW_bf, FEAT, nullptr, nullptr, 0, proj_b,
        nullptr, nullptr, 0, 0, nullptr, h_bf, HIDDEN);

    // initial attention -> z0
    gemm_kernel<2, 2><<<dim3(2, 8), 128>>>(
        h_bf, attnW_bf, HIDDEN, nullptr, nullptr, 0, attn_b,
        nullptr, nullptr, 0, 0, pre, nullptr, FEAT);
    softz_kernel<<<BATCH, 128>>>(pre, features, z_bf, nullptr, nullptr, nullptr, nullptr);

    for (int t = 0; t < TSTEPS; t++) {
        // x = embed_W[word_t] + z @ ztrans_W^T + ztrans_b  -> x (bf16 frag)
        gemm_kernel<2, 2><<<dim3(2, 4), 128>>>(
            z_bf, ztransW_bf, FEAT, nullptr, nullptr, 0, ztrans_b,
            embed_W, captions + t, CAPLEN, WVEC, nullptr, x_bf, WVEC);

        // gates = x @ W_ih^T + h @ W_hh^T + (b_ih + b_hh)  (fp32 row-major)
        gemm_kernel<2, 2><<<dim3(2, 32), 128>>>(
            x_bf, Wih_bf, WVEC, h_bf, Whh_bf, HIDDEN, biasc,
            nullptr, nullptr, 0, 0, gates, nullptr, 4 * HIDDEN);

        // LSTM cell -> c, h (frag); zero rowsum for vocab pass
        lstm_kernel<<<512, 256>>>(gates, cbuf, h_bf, rowsum);

        // logits = h @ vocab_W^T + vocab_b; fused sum(exp) + target gather
        vocab_kernel<<<dim3(2, VOCAB / 128), 256>>>(
            h_bf, vocabW_bf, vocab_b, captions + t + 1, rowsum, tgtlogit);

        // attention pre-activations for z_{t+1}
        gemm_kernel<2, 2><<<dim3(2, 8), 128>>>(
            h_bf, attnW_bf, HIDDEN, nullptr, nullptr, 0, attn_b,
            nullptr, nullptr, 0, 0, pre, nullptr, FEAT);

        // softmax -> z (frag), plus masked loss accumulation (/BATCH folded in)
        softz_kernel<<<BATCH, 128>>>(pre, features, z_bf, rowsum, tgtlogit,
                                     captions + t + 1, out);
    }
}